// round 13
// baseline (speedup 1.0000x reference)
#include <cuda_runtime.h>
#include <cstdint>

#define RADIAL 160
#define RPB 8                         // rows per block (65536 % 8 == 0)
#define ROW_F 480                     // scalars per row
#define F4R 120                       // float4 per row
#define NT 320                        // block size = RPB*40, all compute
#define TOT (RPB * F4R)               // 960 f4
#define GUARD 12                      // zeroed guard f4 each side of sIn
#define SINF4 (TOT + 2 * GUARD)       // 984

struct Params {
    float dt_offset, dt_persist, k, cc, amount;
    float w[5];
    int   D, edge;
    int   p;        // alignment phase 0..3
    int   G2;       // row-local f4 window shift: wq = q + G2
};

__device__ Params g_params;
__device__ float4 g_coefP[RADIAL];    // plane layout: [(bin&3)*40 + (bin>>2)]

__global__ void prep_kernel(const float* __restrict__ offset,
                            const float* __restrict__ persistence,
                            const float* __restrict__ diffusion01,
                            const float* __restrict__ dt_seconds,
                            const float* __restrict__ amount01,
                            const float* __restrict__ spread01) {
    const int bin = threadIdx.x;      // 160 threads

    float dt = fminf(fmaxf(*dt_seconds, 0.0f), 0.05f);
    float dts = dt * 60.0f;
    float off = (*offset) * dts;
    float P   = powf(*persistence, dts);
    float k   = 0.15f * (*diffusion01);
    float cc  = 1.0f - 2.0f * k;
    int   D   = (int)floorf(off);

    float npi = (float)bin + off;
    bool validi = (npi >= 0.0f) && (npi < (float)(RADIAL - 1));
    int lii = min(max((int)floorf(npi), 0), RADIAL - 2);
    int myedge = (validi && (lii != bin + D)) ? 1 : 0;
    int edge = __syncthreads_or(myedge);

    if (bin == 0) {
        g_params.dt_offset  = off;
        g_params.dt_persist = P;
        g_params.k  = k;  g_params.cc = cc;
        g_params.D  = D;  g_params.edge = edge;
        g_params.amount = fminf(fmaxf(*amount01, 0.0f), 1.0f);
        float spread = fminf(fmaxf(*spread01, 0.0f), 1.0f);
        float tight  = 1.0f - spread;
        g_params.w[0] = 0.5f + 0.4f * tight;
        g_params.w[1] = 0.2f * spread + 0.05f;
        g_params.w[2] = 0.12f * spread;
        g_params.w[3] = 0.06f * spread;
        g_params.w[4] = 0.02f * spread;
        int b0 = -3 * (D + 2);                   // row-local tap base
        int p  = ((b0 % 4) + 4) % 4;
        g_params.p  = p;
        g_params.G2 = (b0 - p) / 4;
    }

    // Fused per-bin coefficients: out[bin] = sum_d c[d] * hclip[bin-D-2+d]
    float fade = 1.0f;
    if (bin >= RADIAL - 8) {
        float tt = (float)(RADIAL - 1 - bin) * 0.125f;
        fade = tt * tt;
    }
    float c[4] = {0.0f, 0.0f, 0.0f, 0.0f};
    #pragma unroll
    for (int d = 0; d < 4; d++) {
        int src = bin - D - 2 + d;
        if (src < 0 || src >= RADIAL) continue;
        float nps = (float)src + off;            // same fp ops as reference
        if (!(nps >= 0.0f && nps < (float)(RADIAL - 1))) continue;
        int   ls  = min(max((int)floorf(nps), 0), RADIAL - 2);
        float fr  = nps - (float)ls;
        float wls = (1.0f - fr) * P;
        float wrs = fr * P;
        float sb  = (ls == bin     ? wls : 0.0f) + (ls + 1 == bin     ? wrs : 0.0f);
        float sbm = 0.0f, sbp = 0.0f;
        if (bin >= 1)
            sbm = (ls == bin - 1 ? wls : 0.0f) + (ls + 1 == bin - 1 ? wrs : 0.0f);
        if (bin <= RADIAL - 2)
            sbp = (ls == bin + 1 ? wls : 0.0f) + (ls + 1 == bin + 1 ? wrs : 0.0f);
        c[d] = (cc * sb + k * (sbm + sbp)) * fade;
    }
    g_coefP[(bin & 3) * 40 + (bin >> 2)] = make_float4(c[0], c[1], c[2], c[3]);
}

// ---- PTX helpers ----
__device__ __forceinline__ uint32_t smem_u32(const void* p) {
    uint32_t a;
    asm("{ .reg .u64 t; cvta.to.shared.u64 t, %1; cvt.u32.u64 %0, t; }"
        : "=r"(a) : "l"(p));
    return a;
}

// scalar J (0..23) of window {w0..w5}
template<int J>
__device__ __forceinline__ float gw(const float4 w0, const float4 w1,
                                    const float4 w2, const float4 w3,
                                    const float4 w4, const float4 w5) {
    constexpr int F = J / 4, C = J % 4;
    const float4 v = (F == 0) ? w0 : (F == 1) ? w1 : (F == 2) ? w2
                   : (F == 3) ? w3 : (F == 4) ? w4 : w5;
    if constexpr      (C == 0) return v.x;
    else if constexpr (C == 1) return v.y;
    else if constexpr (C == 2) return v.z;
    else                       return v.w;
}

#define GW(J) gw<(P) + (J)>(w0, w1, w2, w3, w4, w5)
#define TAPE(e, cf) ((cf).x * GW(e) + (cf).y * GW((e) + 3) + \
                     (cf).z * GW((e) + 6) + (cf).w * GW((e) + 9))

template<int P>
__device__ __forceinline__ void apply12(const float4 w0, const float4 w1,
                                        const float4 w2, const float4 w3,
                                        const float4 w4, const float4 w5,
                                        const float4 c0, const float4 c1,
                                        const float4 c2, const float4 c3,
                                        float4& o0, float4& o1, float4& o2) {
    o0.x = TAPE(0, c0);  o0.y = TAPE(1, c0);  o0.z = TAPE(2, c0);  o0.w = TAPE(3, c1);
    o1.x = TAPE(4, c1);  o1.y = TAPE(5, c1);  o1.z = TAPE(6, c2);  o1.w = TAPE(7, c2);
    o2.x = TAPE(8, c2);  o2.y = TAPE(9, c3);  o2.z = TAPE(10, c3); o2.w = TAPE(11, c3);
}

__device__ __forceinline__ float4 clamp01_4(float4 v) {
    v.x = fminf(fmaxf(v.x, 0.0f), 1.0f);
    v.y = fminf(fmaxf(v.y, 0.0f), 1.0f);
    v.z = fminf(fmaxf(v.z, 0.0f), 1.0f);
    v.w = fminf(fmaxf(v.w, 0.0f), 1.0f);
    return v;
}

// generic-path helper: inject + clip one (row, srcbin, ch) from global
__device__ __forceinline__ float loadclip(const float* __restrict__ history,
                                          const float* __restrict__ color_rgb,
                                          long long row, int srcbin, int ch) {
    int sb = min(max(srcbin, 0), RADIAL - 1);
    float v = history[row * ROW_F + sb * 3 + ch];
    if (sb < 5)
        v += color_rgb[row * 3 + ch] * g_params.amount * g_params.w[sb];
    return fminf(fmaxf(v, 0.0f), 1.0f);
}

__global__ __launch_bounds__(NT, 5)
void beat_pulse_tma(const float* __restrict__ history,
                    const float* __restrict__ color_rgb,
                    float* __restrict__ out) {
    __shared__ float4 sIn[SINF4];                 // raw rows + guards; reused for output
    __shared__ float4 sCoef[RADIAL];              // plane-layout coefs
    __shared__ alignas(8) unsigned long long mbar;

    const int t = threadIdx.x;
    const long long base_row = (long long)blockIdx.x * RPB;
    const uint32_t mbar_a = smem_u32(&mbar);

    if (t == 0)
        asm volatile("mbarrier.init.shared.b64 [%0], 1;" :: "r"(mbar_a) : "memory");
    __syncthreads();                              // publish mbar init

    if (t == 0) {
        const uint32_t dst = smem_u32(sIn) + GUARD * 16;
        const float* src = history + base_row * ROW_F;
        asm volatile("mbarrier.arrive.expect_tx.shared.b64 _, [%0], %1;"
                     :: "r"(mbar_a), "r"((uint32_t)(TOT * 16)) : "memory");
        asm volatile(
            "cp.async.bulk.shared::cluster.global.mbarrier::complete_tx::bytes "
            "[%0], [%1], %2, [%3];"
            :: "r"(dst), "l"(src), "r"((uint32_t)(TOT * 16)), "r"(mbar_a)
            : "memory");
    }

    // zero guards (independent of TMA data)
    if (t < 2 * GUARD) {
        int idx = (t < GUARD) ? t : (GUARD + TOT + (t - GUARD));
        sIn[idx] = make_float4(0.f, 0.f, 0.f, 0.f);
    }
    // stage coef planes
    if (t < RADIAL) sCoef[t] = __ldg(&g_coefP[t]);

    // prefetch color for inject threads (independent of TMA)
    const bool isInj = (t >= 64) && (t < 64 + RPB * 4);
    float en0 = 0.f, en1 = 0.f, en2 = 0.f;
    int injRow = 0, injJ = 0;
    if (isInj) {
        int idx = t - 64;
        injRow = idx >> 2;
        injJ   = idx & 3;
        long long b = base_row + injRow;
        float amount = g_params.amount;
        en0 = color_rgb[b * 3 + 0] * amount;
        en1 = color_rgb[b * 3 + 1] * amount;
        en2 = color_rgb[b * 3 + 2] * amount;
    }

    // wait for TMA (acquire)
    {
        uint32_t done;
        asm volatile(
            "{\n\t.reg .pred p;\n\t"
            "mbarrier.try_wait.parity.acquire.cta.shared::cta.b64 p, [%1], 0;\n\t"
            "selp.b32 %0, 1, 0, p;\n\t}"
            : "=r"(done) : "r"(mbar_a) : "memory");
        if (!done) {
            asm volatile(
                "{\n\t.reg .pred P1;\n\t"
                "WL_%=:\n\t"
                "mbarrier.try_wait.parity.acquire.cta.shared::cta.b64 P1, [%0], 0, 0x989680;\n\t"
                "@P1 bra.uni WD_%=;\n\t"
                "bra.uni WL_%=;\n\t"
                "WD_%=:\n\t}"
                :: "r"(mbar_a) : "memory");
        }
    }

    // inject (raw add; clip happens at window read) — 4 f4 per row
    if (isInj) {
        float en[3] = {en0, en1, en2};
        float4 v = sIn[GUARD + injRow * F4R + injJ];
        float vals[4] = {v.x, v.y, v.z, v.w};
        #pragma unroll
        for (int e = 0; e < 4; e++) {
            int sidx = injJ * 4 + e;
            int bin  = sidx / 3;
            int ch   = sidx - bin * 3;
            if (bin < 5) vals[e] += en[ch] * g_params.w[bin];
        }
        sIn[GUARD + injRow * F4R + injJ] = make_float4(vals[0], vals[1], vals[2], vals[3]);
    }
    __syncthreads();

    if (!g_params.edge) {
        // ---- fast path: 12 scalars (4 bins) per thread ----
        const int row = t / 40;
        const int u40 = t - row * 40;
        const int q   = 3 * u40;

        int wb = GUARD + row * F4R + q + g_params.G2;
        wb = min(max(wb, 0), SINF4 - 6);
        float4 w0 = clamp01_4(sIn[wb + 0]);
        float4 w1 = clamp01_4(sIn[wb + 1]);
        float4 w2 = clamp01_4(sIn[wb + 2]);
        float4 w3 = clamp01_4(sIn[wb + 3]);
        float4 w4 = clamp01_4(sIn[wb + 4]);
        float4 w5 = clamp01_4(sIn[wb + 5]);

        float4 c0 = sCoef[0 * 40 + u40];
        float4 c1 = sCoef[1 * 40 + u40];
        float4 c2 = sCoef[2 * 40 + u40];
        float4 c3 = sCoef[3 * 40 + u40];

        float4 o0, o1, o2;
        switch (g_params.p) {                     // uniform branch
            case 0:  apply12<0>(w0,w1,w2,w3,w4,w5,c0,c1,c2,c3,o0,o1,o2); break;
            case 1:  apply12<1>(w0,w1,w2,w3,w4,w5,c0,c1,c2,c3,o0,o1,o2); break;
            case 2:  apply12<2>(w0,w1,w2,w3,w4,w5,c0,c1,c2,c3,o0,o1,o2); break;
            default: apply12<3>(w0,w1,w2,w3,w4,w5,c0,c1,c2,c3,o0,o1,o2); break;
        }

        // all window reads complete before results overwrite sIn
        __syncthreads();
        sIn[GUARD + row * F4R + q + 0] = o0;
        sIn[GUARD + row * F4R + q + 1] = o1;
        sIn[GUARD + row * F4R + q + 2] = o2;

        asm volatile("fence.proxy.async.shared::cta;" ::: "memory");
        __syncthreads();

        if (t == 0) {
            const uint32_t src = smem_u32(sIn) + GUARD * 16;
            float* dst = out + base_row * ROW_F;
            asm volatile("cp.async.bulk.global.shared::cta.bulk_group [%0], [%1], %2;"
                         :: "l"(dst), "r"(src), "r"((uint32_t)(TOT * 16)) : "memory");
            asm volatile("cp.async.bulk.commit_group;" ::: "memory");
            asm volatile("cp.async.bulk.wait_group 0;" ::: "memory");
        }
    } else {
        // ---- generic fallback from global (never taken for bench params) ----
        const float off = g_params.dt_offset;
        const float P   = g_params.dt_persist;
        const float k   = g_params.k;
        const float cc  = g_params.cc;
        const int   D   = g_params.D;
        const int row = t / 40;
        const int u40 = t - row * 40;
        const long long grow = base_row + row;

        #pragma unroll
        for (int e = 0; e < 12; e++) {
            int s   = 12 * u40 + e;
            int bin = s / 3;
            int ch  = s - 3 * bin;
            float adv[3];
            #pragma unroll
            for (int bo = -1; bo <= 1; bo++) {
                int bb = bin + bo;
                float a = 0.0f;
                if (bb >= 0 && bb < RADIAL) {
                    #pragma unroll
                    for (int d = -2; d <= 1; d++) {
                        int i = bb - D + d;
                        float np = (float)i + off;
                        float lf = floorf(np);
                        int   li = (int)lf;
                        float fr = np - lf;
                        bool vs = (i >= 0) & (i < RADIAL) &
                                  (np >= 0.0f) & (np < (float)(RADIAL - 1));
                        float wl = (vs && li == bb)     ? (1.0f - fr) * P : 0.0f;
                        float wr = (vs && li == bb - 1) ? fr * P          : 0.0f;
                        float w = wl + wr;
                        if (w != 0.0f)
                            a += w * loadclip(history, color_rgb, grow, i, ch);
                    }
                }
                adv[bo + 1] = a;
            }
            float fade = 1.0f;
            if (bin >= RADIAL - 8) {
                float tt = (float)(RADIAL - 1 - bin) * 0.125f;
                fade = tt * tt;
            }
            out[grow * ROW_F + s] = (cc * adv[1] + k * adv[0] + k * adv[2]) * fade;
        }
    }
}

extern "C" void kernel_launch(void* const* d_in, const int* in_sizes, int n_in,
                              void* d_out, int out_size) {
    const float* history     = (const float*)d_in[0];
    const float* color_rgb   = (const float*)d_in[1];
    const float* offset      = (const float*)d_in[2];
    const float* persistence = (const float*)d_in[3];
    const float* diffusion01 = (const float*)d_in[4];
    const float* dt_seconds  = (const float*)d_in[5];
    const float* amount01    = (const float*)d_in[6];
    const float* spread01    = (const float*)d_in[7];
    float* out = (float*)d_out;

    int nrows = in_sizes[0] / ROW_F;              // 65536
    int grid  = nrows / RPB;                      // 8192 (divides exactly)

    prep_kernel<<<1, RADIAL>>>(offset, persistence, diffusion01, dt_seconds,
                               amount01, spread01);
    beat_pulse_tma<<<grid, NT>>>(history, color_rgb, out);
}

// round 15
// speedup vs baseline: 1.6435x; 1.6435x over previous
#include <cuda_runtime.h>
#include <cstdint>

#define RADIAL 160
#define RPB 8                         // rows per tile
#define TILES 2                       // tiles per block
#define ROW_F 480                     // scalars per row
#define F4R 120                       // float4 per row
#define NT 320                        // block size = RPB*40
#define TOT (RPB * F4R)               // 960 f4 per tile
#define GUARD 12                      // zeroed guard f4 each side
#define SINF4 (TOT + 2 * GUARD)       // 984

struct Params {
    float dt_offset, dt_persist, k, cc, amount;
    float w[5];
    int   D, edge;
    int   p;        // alignment phase 0..3
    int   G2;       // row-local f4 window shift
};

__device__ Params g_params;
__device__ float4 g_coefP[RADIAL];    // plane layout: [(bin&3)*40 + (bin>>2)]

__global__ void prep_kernel(const float* __restrict__ offset,
                            const float* __restrict__ persistence,
                            const float* __restrict__ diffusion01,
                            const float* __restrict__ dt_seconds,
                            const float* __restrict__ amount01,
                            const float* __restrict__ spread01) {
    const int bin = threadIdx.x;      // 160 threads

    float dt = fminf(fmaxf(*dt_seconds, 0.0f), 0.05f);
    float dts = dt * 60.0f;
    float off = (*offset) * dts;
    float P   = powf(*persistence, dts);
    float k   = 0.15f * (*diffusion01);
    float cc  = 1.0f - 2.0f * k;
    int   D   = (int)floorf(off);

    float npi = (float)bin + off;
    bool validi = (npi >= 0.0f) && (npi < (float)(RADIAL - 1));
    int lii = min(max((int)floorf(npi), 0), RADIAL - 2);
    int myedge = (validi && (lii != bin + D)) ? 1 : 0;
    int edge = __syncthreads_or(myedge);

    if (bin == 0) {
        g_params.dt_offset  = off;
        g_params.dt_persist = P;
        g_params.k  = k;  g_params.cc = cc;
        g_params.D  = D;  g_params.edge = edge;
        g_params.amount = fminf(fmaxf(*amount01, 0.0f), 1.0f);
        float spread = fminf(fmaxf(*spread01, 0.0f), 1.0f);
        float tight  = 1.0f - spread;
        g_params.w[0] = 0.5f + 0.4f * tight;
        g_params.w[1] = 0.2f * spread + 0.05f;
        g_params.w[2] = 0.12f * spread;
        g_params.w[3] = 0.06f * spread;
        g_params.w[4] = 0.02f * spread;
        int b0 = -3 * (D + 2);
        int p  = ((b0 % 4) + 4) % 4;
        g_params.p  = p;
        g_params.G2 = (b0 - p) / 4;
    }

    float fade = 1.0f;
    if (bin >= RADIAL - 8) {
        float tt = (float)(RADIAL - 1 - bin) * 0.125f;
        fade = tt * tt;
    }
    float c[4] = {0.0f, 0.0f, 0.0f, 0.0f};
    #pragma unroll
    for (int d = 0; d < 4; d++) {
        int src = bin - D - 2 + d;
        if (src < 0 || src >= RADIAL) continue;
        float nps = (float)src + off;            // same fp ops as reference
        if (!(nps >= 0.0f && nps < (float)(RADIAL - 1))) continue;
        int   ls  = min(max((int)floorf(nps), 0), RADIAL - 2);
        float fr  = nps - (float)ls;
        float wls = (1.0f - fr) * P;
        float wrs = fr * P;
        float sb  = (ls == bin     ? wls : 0.0f) + (ls + 1 == bin     ? wrs : 0.0f);
        float sbm = 0.0f, sbp = 0.0f;
        if (bin >= 1)
            sbm = (ls == bin - 1 ? wls : 0.0f) + (ls + 1 == bin - 1 ? wrs : 0.0f);
        if (bin <= RADIAL - 2)
            sbp = (ls == bin + 1 ? wls : 0.0f) + (ls + 1 == bin + 1 ? wrs : 0.0f);
        c[d] = (cc * sb + k * (sbm + sbp)) * fade;
    }
    g_coefP[(bin & 3) * 40 + (bin >> 2)] = make_float4(c[0], c[1], c[2], c[3]);
}

// ---- PTX helpers ----
__device__ __forceinline__ uint32_t smem_u32(const void* p) {
    uint32_t a;
    asm("{ .reg .u64 t; cvta.to.shared.u64 t, %1; cvt.u32.u64 %0, t; }"
        : "=r"(a) : "l"(p));
    return a;
}

__device__ __forceinline__ void mbar_wait(uint32_t mbar_a) {
    uint32_t done;
    asm volatile(
        "{\n\t.reg .pred p;\n\t"
        "mbarrier.try_wait.parity.acquire.cta.shared::cta.b64 p, [%1], 0;\n\t"
        "selp.b32 %0, 1, 0, p;\n\t}"
        : "=r"(done) : "r"(mbar_a) : "memory");
    if (!done) {
        asm volatile(
            "{\n\t.reg .pred P1;\n\t"
            "WL_%=:\n\t"
            "mbarrier.try_wait.parity.acquire.cta.shared::cta.b64 P1, [%0], 0, 0x989680;\n\t"
            "@P1 bra.uni WD_%=;\n\t"
            "bra.uni WL_%=;\n\t"
            "WD_%=:\n\t}"
            :: "r"(mbar_a) : "memory");
    }
}

// scalar J (0..23) of window {w0..w5}
template<int J>
__device__ __forceinline__ float gw(const float4 w0, const float4 w1,
                                    const float4 w2, const float4 w3,
                                    const float4 w4, const float4 w5) {
    constexpr int F = J / 4, C = J % 4;
    const float4 v = (F == 0) ? w0 : (F == 1) ? w1 : (F == 2) ? w2
                   : (F == 3) ? w3 : (F == 4) ? w4 : w5;
    if constexpr      (C == 0) return v.x;
    else if constexpr (C == 1) return v.y;
    else if constexpr (C == 2) return v.z;
    else                       return v.w;
}

#define GW(J) gw<(P) + (J)>(w0, w1, w2, w3, w4, w5)
#define TAPE(e, cf) ((cf).x * GW(e) + (cf).y * GW((e) + 3) + \
                     (cf).z * GW((e) + 6) + (cf).w * GW((e) + 9))

template<int P>
__device__ __forceinline__ void apply12(const float4 w0, const float4 w1,
                                        const float4 w2, const float4 w3,
                                        const float4 w4, const float4 w5,
                                        const float4 c0, const float4 c1,
                                        const float4 c2, const float4 c3,
                                        float4& o0, float4& o1, float4& o2) {
    o0.x = TAPE(0, c0);  o0.y = TAPE(1, c0);  o0.z = TAPE(2, c0);  o0.w = TAPE(3, c1);
    o1.x = TAPE(4, c1);  o1.y = TAPE(5, c1);  o1.z = TAPE(6, c2);  o1.w = TAPE(7, c2);
    o2.x = TAPE(8, c2);  o2.y = TAPE(9, c3);  o2.z = TAPE(10, c3); o2.w = TAPE(11, c3);
}

__device__ __forceinline__ float4 clamp01_4(float4 v) {
    v.x = fminf(fmaxf(v.x, 0.0f), 1.0f);
    v.y = fminf(fmaxf(v.y, 0.0f), 1.0f);
    v.z = fminf(fmaxf(v.z, 0.0f), 1.0f);
    v.w = fminf(fmaxf(v.w, 0.0f), 1.0f);
    return v;
}

// generic-path helper: inject + clip one (row, srcbin, ch) from global
__device__ __forceinline__ float loadclip(const float* __restrict__ history,
                                          const float* __restrict__ color_rgb,
                                          long long row, int srcbin, int ch) {
    int sb = min(max(srcbin, 0), RADIAL - 1);
    float v = history[row * ROW_F + sb * 3 + ch];
    if (sb < 5)
        v += color_rgb[row * 3 + ch] * g_params.amount * g_params.w[sb];
    return fminf(fmaxf(v, 0.0f), 1.0f);
}

__global__ __launch_bounds__(NT, 4)
void beat_pulse_tma(const float* __restrict__ history,
                    const float* __restrict__ color_rgb,
                    float* __restrict__ out) {
    __shared__ float4 sA[SINF4];                  // tile 0 (input, then output)
    __shared__ float4 sB[SINF4];                  // tile 1 (input, then output)
    __shared__ float4 sCoef[RADIAL];
    __shared__ alignas(8) unsigned long long mbar[TILES];

    const int t = threadIdx.x;
    const long long base_row = (long long)blockIdx.x * (RPB * TILES);
    const uint32_t mbar_a0 = smem_u32(&mbar[0]);
    const uint32_t mbar_a1 = smem_u32(&mbar[1]);

    if (t == 0) {
        asm volatile("mbarrier.init.shared.b64 [%0], 1;" :: "r"(mbar_a0) : "memory");
        asm volatile("mbarrier.init.shared.b64 [%0], 1;" :: "r"(mbar_a1) : "memory");
    }
    __syncthreads();                              // publish mbar init

    // issue BOTH tile loads up front
    if (t == 0) {
        #pragma unroll
        for (int tk = 0; tk < TILES; tk++) {
            const uint32_t mb  = (tk == 0) ? mbar_a0 : mbar_a1;
            const uint32_t dst = smem_u32(tk == 0 ? sA : sB) + GUARD * 16;
            const float* src = history + (base_row + (long long)tk * RPB) * ROW_F;
            asm volatile("mbarrier.arrive.expect_tx.shared.b64 _, [%0], %1;"
                         :: "r"(mb), "r"((uint32_t)(TOT * 16)) : "memory");
            asm volatile(
                "cp.async.bulk.shared::cluster.global.mbarrier::complete_tx::bytes "
                "[%0], [%1], %2, [%3];"
                :: "r"(dst), "l"(src), "r"((uint32_t)(TOT * 16)), "r"(mb)
                : "memory");
        }
    }

    // zero guards of both buffers (independent of TMA data regions)
    if (t < 2 * GUARD) {
        int idx = (t < GUARD) ? t : (GUARD + TOT + (t - GUARD));
        sA[idx] = make_float4(0.f, 0.f, 0.f, 0.f);
        sB[idx] = make_float4(0.f, 0.f, 0.f, 0.f);
    }
    // stage coef planes (read AFTER the tile-0 __syncthreads below)
    if (t < RADIAL) sCoef[t] = __ldg(&g_coefP[t]);

    // prefetch inject colors for both tiles (independent of TMA)
    const bool isInj = (t >= 64) && (t < 64 + RPB * 4);
    float enA[3] = {0.f, 0.f, 0.f}, enB[3] = {0.f, 0.f, 0.f};
    int injRow = 0, injJ = 0;
    if (isInj) {
        int idx = t - 64;
        injRow = idx >> 2;
        injJ   = idx & 3;
        float amount = g_params.amount;
        long long b0 = base_row + injRow;
        long long b1 = base_row + RPB + injRow;
        enA[0] = color_rgb[b0 * 3 + 0] * amount;
        enA[1] = color_rgb[b0 * 3 + 1] * amount;
        enA[2] = color_rgb[b0 * 3 + 2] * amount;
        enB[0] = color_rgb[b1 * 3 + 0] * amount;
        enB[1] = color_rgb[b1 * 3 + 1] * amount;
        enB[2] = color_rgb[b1 * 3 + 2] * amount;
    }

    const int edge = g_params.edge;

    if (!edge) {
        const int row = t / 40;
        const int u40 = t - row * 40;
        const int q   = 3 * u40;

        float4 c0, c1, c2, c3;                    // loaded after tile-0 sync

        #pragma unroll
        for (int tk = 0; tk < TILES; tk++) {
            float4* sT = (tk == 0) ? sA : sB;
            const uint32_t mb = (tk == 0) ? mbar_a0 : mbar_a1;
            const float* en = (tk == 0) ? enA : enB;

            mbar_wait(mb);                        // tile data resident

            // inject (raw add; clip at window read)
            if (isInj) {
                float4 v = sT[GUARD + injRow * F4R + injJ];
                float vals[4] = {v.x, v.y, v.z, v.w};
                #pragma unroll
                for (int e = 0; e < 4; e++) {
                    int sidx = injJ * 4 + e;
                    int bin  = sidx / 3;
                    int ch   = sidx - bin * 3;
                    if (bin < 5) vals[e] += en[ch] * g_params.w[bin];
                }
                sT[GUARD + injRow * F4R + injJ] =
                    make_float4(vals[0], vals[1], vals[2], vals[3]);
            }
            __syncthreads();                      // orders inject AND sCoef writes

            if (tk == 0) {                        // FIX: read coefs after barrier
                c0 = sCoef[0 * 40 + u40];
                c1 = sCoef[1 * 40 + u40];
                c2 = sCoef[2 * 40 + u40];
                c3 = sCoef[3 * 40 + u40];
            }

            int wb = GUARD + row * F4R + q + g_params.G2;
            wb = min(max(wb, 0), SINF4 - 6);
            float4 w0 = clamp01_4(sT[wb + 0]);
            float4 w1 = clamp01_4(sT[wb + 1]);
            float4 w2 = clamp01_4(sT[wb + 2]);
            float4 w3 = clamp01_4(sT[wb + 3]);
            float4 w4 = clamp01_4(sT[wb + 4]);
            float4 w5 = clamp01_4(sT[wb + 5]);

            float4 o0, o1, o2;
            switch (g_params.p) {                 // uniform branch
                case 0:  apply12<0>(w0,w1,w2,w3,w4,w5,c0,c1,c2,c3,o0,o1,o2); break;
                case 1:  apply12<1>(w0,w1,w2,w3,w4,w5,c0,c1,c2,c3,o0,o1,o2); break;
                case 2:  apply12<2>(w0,w1,w2,w3,w4,w5,c0,c1,c2,c3,o0,o1,o2); break;
                default: apply12<3>(w0,w1,w2,w3,w4,w5,c0,c1,c2,c3,o0,o1,o2); break;
            }

            __syncthreads();                      // all reads done before overwrite
            sT[GUARD + row * F4R + q + 0] = o0;
            sT[GUARD + row * F4R + q + 1] = o1;
            sT[GUARD + row * F4R + q + 2] = o2;

            asm volatile("fence.proxy.async.shared::cta;" ::: "memory");
            __syncthreads();                      // outputs visible to async proxy

            if (t == 0) {                         // commit store, DON'T wait yet
                const uint32_t src = smem_u32(sT) + GUARD * 16;
                float* dst = out + (base_row + (long long)tk * RPB) * ROW_F;
                asm volatile("cp.async.bulk.global.shared::cta.bulk_group [%0], [%1], %2;"
                             :: "l"(dst), "r"(src), "r"((uint32_t)(TOT * 16)) : "memory");
                asm volatile("cp.async.bulk.commit_group;" ::: "memory");
            }
        }
        if (t == 0)
            asm volatile("cp.async.bulk.wait_group 0;" ::: "memory");
    } else {
        // ---- generic fallback from global (never taken for bench params) ----
        const float off = g_params.dt_offset;
        const float P   = g_params.dt_persist;
        const float k   = g_params.k;
        const float cc  = g_params.cc;
        const int   D   = g_params.D;
        const int row = t / 40;
        const int u40 = t - row * 40;

        for (int tk = 0; tk < TILES; tk++) {
            const long long grow = base_row + (long long)tk * RPB + row;
            #pragma unroll
            for (int e = 0; e < 12; e++) {
                int s   = 12 * u40 + e;
                int bin = s / 3;
                int ch  = s - 3 * bin;
                float adv[3];
                #pragma unroll
                for (int bo = -1; bo <= 1; bo++) {
                    int bb = bin + bo;
                    float a = 0.0f;
                    if (bb >= 0 && bb < RADIAL) {
                        #pragma unroll
                        for (int d = -2; d <= 1; d++) {
                            int i = bb - D + d;
                            float np = (float)i + off;
                            float lf = floorf(np);
                            int   li = (int)lf;
                            float fr = np - lf;
                            bool vs = (i >= 0) & (i < RADIAL) &
                                      (np >= 0.0f) & (np < (float)(RADIAL - 1));
                            float wl = (vs && li == bb)     ? (1.0f - fr) * P : 0.0f;
                            float wr = (vs && li == bb - 1) ? fr * P          : 0.0f;
                            float w = wl + wr;
                            if (w != 0.0f)
                                a += w * loadclip(history, color_rgb, grow, i, ch);
                        }
                    }
                    adv[bo + 1] = a;
                }
                float fade = 1.0f;
                if (bin >= RADIAL - 8) {
                    float tt = (float)(RADIAL - 1 - bin) * 0.125f;
                    fade = tt * tt;
                }
                out[grow * ROW_F + s] = (cc * adv[1] + k * adv[0] + k * adv[2]) * fade;
            }
        }
    }
}

extern "C" void kernel_launch(void* const* d_in, const int* in_sizes, int n_in,
                              void* d_out, int out_size) {
    const float* history     = (const float*)d_in[0];
    const float* color_rgb   = (const float*)d_in[1];
    const float* offset      = (const float*)d_in[2];
    const float* persistence = (const float*)d_in[3];
    const float* diffusion01 = (const float*)d_in[4];
    const float* dt_seconds  = (const float*)d_in[5];
    const float* amount01    = (const float*)d_in[6];
    const float* spread01    = (const float*)d_in[7];
    float* out = (float*)d_out;

    int nrows = in_sizes[0] / ROW_F;              // 65536
    int grid  = nrows / (RPB * TILES);            // 4096 (divides exactly)

    prep_kernel<<<1, RADIAL>>>(offset, persistence, diffusion01, dt_seconds,
                               amount01, spread01);
    beat_pulse_tma<<<grid, NT>>>(history, color_rgb, out);
}